// round 1
// baseline (speedup 1.0000x reference)
#include <cuda_runtime.h>
#include <math.h>

#define BB 2
#define SS 4096
#define DM 768
#define HH 12
#define HD 64
#define OUTN 512
#define SCH 16   // s-split chunks for y partial accumulation

// ---------------- scratch (device globals; no allocation allowed) ----------
__device__ float g_qg[BB*DM];            // qg row 0, scaled: [b][h*64+d]
__device__ float g_u[BB*DM*HH];          // folded key weights: [b][m][h]
__device__ float g_sbias[BB*HH];
__device__ float g_scores[BB*HH*SS];     // scores, then softmax probs (in place)
__device__ float g_ypart[SCH*BB*HH*DM];  // partial y sums
__device__ float g_og[BB*DM];
__device__ float g_attn0[BB*DM];
__device__ float g_pooled[BB*DM];

// ---------------- K1a: qg0[b,o] = (x[b,0,:] @ wqg[:,o] + bqg[o]) * 0.125 ----
// grid = BB*12 blocks, 256 thr. 64 outputs/block, 4-way dot split.
__global__ void k_qg(const float* __restrict__ x, const float* __restrict__ wqg,
                     const float* __restrict__ bqg) {
    int blk = blockIdx.x; int b = blk / 12, ob = blk % 12;
    int t = threadIdx.x;
    __shared__ float x0[DM];
    for (int i = t; i < DM; i += 256) x0[i] = x[(size_t)b*SS*DM + i];
    __syncthreads();
    int o = ob*64 + (t >> 2);
    int part = t & 3;
    float acc = 0.f;
    const float* wc = wqg + o;
    #pragma unroll 8
    for (int i = 0; i < 192; i++) {
        int m = part*192 + i;
        acc += x0[m] * wc[(size_t)m*DM];
    }
    acc += __shfl_down_sync(0xffffffffu, acc, 2, 4);
    acc += __shfl_down_sync(0xffffffffu, acc, 1, 4);
    if (part == 0) g_qg[b*DM + o] = (acc + bqg[o]) * 0.125f;
}

// ---------------- K1b: u[b,m,h] = sum_d wkg[m,h*64+d]*qg[b,h,d]; sbias -----
// grid = BB*HH*DM/256 = 72 blocks.
__global__ void k_u(const float* __restrict__ wkg, const float* __restrict__ bkg) {
    int i = blockIdx.x*256 + threadIdx.x;          // 0..18431
    int b = i / (HH*DM); int r = i % (HH*DM);
    int h = r / DM; int m = r % DM;
    const float* q = g_qg + b*DM + h*HD;
    const float* w = wkg + (size_t)m*DM + h*HD;
    float acc = 0.f;
    #pragma unroll
    for (int d = 0; d < HD; d++) acc += q[d] * w[d];
    g_u[(b*DM + m)*HH + h] = acc;
    if (m == 0) {
        float sb = 0.f;
        #pragma unroll
        for (int d = 0; d < HD; d++) sb += q[d] * bkg[h*HD + d];
        g_sbias[b*HH + h] = sb;
    }
}

// ---------------- K2: scores[b,h,s] = x[b,s,:] . u[b,:,h] + sbias ----------
// grid = BB*(SS/32) = 256 blocks, 256 thr. 32 rows/block, 8-way dot split.
__global__ void k_scores(const float* __restrict__ x) {
    int blk = blockIdx.x; int b = blk >> 7; int rb = blk & 127;
    int t = threadIdx.x;
    __shared__ __align__(16) float u_s[DM*HH];     // [m][h], 36 KB
    __shared__ float sb_s[HH];
    for (int i = t; i < DM*HH; i += 256) u_s[i] = g_u[b*DM*HH + i];
    if (t < HH) sb_s[t] = g_sbias[b*HH + t];
    __syncthreads();
    int row = rb*32 + (t >> 3);
    int p = t & 7;
    const float* xr = x + ((size_t)b*SS + row)*DM;
    float acc[HH];
    #pragma unroll
    for (int h = 0; h < HH; h++) acc[h] = 0.f;
    #pragma unroll 4
    for (int i = 0; i < 96; i++) {
        int m = i*8 + p;                           // stride-8 interleave: conflict-free
        float xv = xr[m];
        const float4* u4 = (const float4*)(u_s + m*HH);
        float4 a = u4[0], c = u4[1], e = u4[2];
        acc[0] += xv*a.x;  acc[1] += xv*a.y;  acc[2]  += xv*a.z;  acc[3]  += xv*a.w;
        acc[4] += xv*c.x;  acc[5] += xv*c.y;  acc[6]  += xv*c.z;  acc[7]  += xv*c.w;
        acc[8] += xv*e.x;  acc[9] += xv*e.y;  acc[10] += xv*e.z;  acc[11] += xv*e.w;
    }
    #pragma unroll
    for (int off = 4; off; off >>= 1) {
        #pragma unroll
        for (int h = 0; h < HH; h++)
            acc[h] += __shfl_down_sync(0xffffffffu, acc[h], off, 8);
    }
    if (p == 0) {
        #pragma unroll
        for (int h = 0; h < HH; h++)
            g_scores[((size_t)(b*HH + h))*SS + row] = acc[h] + sb_s[h];
    }
}

// ---------------- K3: softmax over s per (b,h), in place --------------------
// grid = BB*HH = 24 blocks, 256 thr.
__global__ void k_softmax() {
    int bh = blockIdx.x; int t = threadIdx.x;
    __shared__ float buf[SS];
    __shared__ float red[256];
    float* sc = g_scores + (size_t)bh*SS;
    float mx = -1e30f;
    for (int i = t; i < SS; i += 256) { float v = sc[i]; buf[i] = v; mx = fmaxf(mx, v); }
    red[t] = mx; __syncthreads();
    for (int o = 128; o; o >>= 1) { if (t < o) red[t] = fmaxf(red[t], red[t+o]); __syncthreads(); }
    mx = red[0]; __syncthreads();
    float sum = 0.f;
    for (int i = t; i < SS; i += 256) { float e = __expf(buf[i] - mx); buf[i] = e; sum += e; }
    red[t] = sum; __syncthreads();
    for (int o = 128; o; o >>= 1) { if (t < o) red[t] += red[t+o]; __syncthreads(); }
    float inv = 1.f / red[0]; __syncthreads();
    for (int i = t; i < SS; i += 256) sc[i] = buf[i] * inv;
}

// ---------------- K4: ypart[sc,b,h,m] = sum_{s in chunk} p[b,h,s]*x[b,s,m] --
// grid = BB*3*SCH = 96 blocks, 256 thr. thread owns one column m.
__global__ void k_ypart(const float* __restrict__ x) {
    int blk = blockIdx.x;
    int sc  = blk & 15;
    int col = (blk >> 4) % 3;
    int b   = blk / 48;
    int t = threadIdx.x;
    int m = col*256 + t;
    int s0 = sc*256;
    __shared__ float pg[HH*256];
    for (int i = t; i < HH*256; i += 256) {
        int h = i >> 8; int s = i & 255;
        pg[i] = g_scores[((size_t)(b*HH + h))*SS + s0 + s];
    }
    __syncthreads();
    float acc[HH];
    #pragma unroll
    for (int h = 0; h < HH; h++) acc[h] = 0.f;
    const float* xp = x + ((size_t)b*SS + s0)*DM + m;
    for (int s = 0; s < 256; s++) {
        float xv = xp[(size_t)s*DM];
        #pragma unroll
        for (int h = 0; h < HH; h++) acc[h] += pg[h*256 + s] * xv;
    }
    #pragma unroll
    for (int h = 0; h < HH; h++)
        g_ypart[(((size_t)sc*BB + b)*HH + h)*DM + m] = acc[h];
}

// ---------------- K5: og[b,h*64+d] = sum_m y[b,h,m]*wvg[m,h*64+d] + bvg -----
// grid = BB*HH = 24 blocks, 256 thr. Reduces ypart, then 64 outputs x 4-split.
__global__ void k_og(const float* __restrict__ wvg, const float* __restrict__ bvg) {
    int blk = blockIdx.x; int b = blk / HH; int h = blk % HH;
    int t = threadIdx.x;
    __shared__ float y_s[DM];
    for (int j = t; j < DM; j += 256) {
        float s = 0.f;
        #pragma unroll
        for (int sc = 0; sc < SCH; sc++)
            s += g_ypart[(((size_t)sc*BB + b)*HH + h)*DM + j];
        y_s[j] = s;
    }
    __syncthreads();
    int o = h*HD + (t >> 2);
    int part = t & 3;
    float acc = 0.f;
    const float* w = wvg + o;
    #pragma unroll 8
    for (int i = 0; i < 192; i++) {
        int m = part*192 + i;
        acc += y_s[m] * w[(size_t)m*DM];
    }
    acc += __shfl_down_sync(0xffffffffu, acc, 2, 4);
    acc += __shfl_down_sync(0xffffffffu, acc, 1, 4);
    if (part == 0) g_og[b*DM + o] = acc + bvg[o];
}

// ---------------- K6/K7: generic 768x768 GEMV, optional tanh ---------------
// grid = BB*12 = 24 blocks, 256 thr.
__global__ void k_gemv768(const float* __restrict__ in, const float* __restrict__ w,
                          const float* __restrict__ bias, float* __restrict__ out,
                          int dotanh) {
    int blk = blockIdx.x; int b = blk / 12; int ob = blk % 12;
    int t = threadIdx.x;
    __shared__ float in_s[DM];
    for (int i = t; i < DM; i += 256) in_s[i] = in[b*DM + i];
    __syncthreads();
    int o = ob*64 + (t >> 2);
    int part = t & 3;
    float acc = 0.f;
    const float* wc = w + o;
    #pragma unroll 8
    for (int i = 0; i < 192; i++) {
        int m = part*192 + i;
        acc += in_s[m] * wc[(size_t)m*DM];
    }
    acc += __shfl_down_sync(0xffffffffu, acc, 2, 4);
    acc += __shfl_down_sync(0xffffffffu, acc, 1, 4);
    if (part == 0) {
        float v = acc + bias[o];
        out[b*DM + o] = dotanh ? tanhf(v) : v;
    }
}

// ---------------- K8: out[b,o] = pooled[b,:] @ wfc[:,o] + bfc[o] -----------
// grid = BB*8 = 16 blocks, 256 thr.
__global__ void k_final(const float* __restrict__ wfc, const float* __restrict__ bfc,
                        float* __restrict__ out) {
    int blk = blockIdx.x; int b = blk / 8; int ob = blk % 8;
    int t = threadIdx.x;
    __shared__ float in_s[DM];
    for (int i = t; i < DM; i += 256) in_s[i] = g_pooled[b*DM + i];
    __syncthreads();
    int o = ob*64 + (t >> 2);
    int part = t & 3;
    float acc = 0.f;
    #pragma unroll 8
    for (int i = 0; i < 192; i++) {
        int m = part*192 + i;
        acc += in_s[m] * wfc[(size_t)m*OUTN + o];
    }
    acc += __shfl_down_sync(0xffffffffu, acc, 2, 4);
    acc += __shfl_down_sync(0xffffffffu, acc, 1, 4);
    if (part == 0) out[b*OUTN + o] = acc + bfc[o];
}

// ---------------- launch ----------------------------------------------------
extern "C" void kernel_launch(void* const* d_in, const int* in_sizes, int n_in,
                              void* d_out, int out_size) {
    const float* x   = (const float*)d_in[0];
    const float* wqg = (const float*)d_in[7];
    const float* bqg = (const float*)d_in[8];
    const float* wkg = (const float*)d_in[9];
    const float* bkg = (const float*)d_in[10];
    const float* wvg = (const float*)d_in[11];
    const float* bvg = (const float*)d_in[12];
    const float* wo  = (const float*)d_in[13];
    const float* bo  = (const float*)d_in[14];
    const float* wp  = (const float*)d_in[15];
    const float* bp  = (const float*)d_in[16];
    const float* wfc = (const float*)d_in[17];
    const float* bfc = (const float*)d_in[18];
    float* out = (float*)d_out;

    float *p_og, *p_attn0, *p_pooled;
    cudaGetSymbolAddress((void**)&p_og, g_og);
    cudaGetSymbolAddress((void**)&p_attn0, g_attn0);
    cudaGetSymbolAddress((void**)&p_pooled, g_pooled);

    k_qg<<<BB*12, 256>>>(x, wqg, bqg);
    k_u<<<(BB*HH*DM)/256, 256>>>(wkg, bkg);
    k_scores<<<BB*(SS/32), 256>>>(x);
    k_softmax<<<BB*HH, 256>>>();
    k_ypart<<<BB*3*SCH, 256>>>(x);
    k_og<<<BB*HH, 256>>>(wvg, bvg);
    k_gemv768<<<BB*12, 256>>>(p_og, wo, bo, p_attn0, 0);
    k_gemv768<<<BB*12, 256>>>(p_attn0, wp, bp, p_pooled, 1);
    k_final<<<BB*8, 256>>>(wfc, bfc, out);
}

// round 2
// speedup vs baseline: 1.3364x; 1.3364x over previous
#include <cuda_runtime.h>
#include <math.h>

#define BB 2
#define SS 4096
#define DM 768
#define HH 12
#define HD 64
#define OUTN 512
#define CHROWS 32            // rows per block in fused main kernel
#define NCH (SS/CHROWS)      // 128 chunks per batch

// ---------------- scratch ---------------------------------------------------
__device__ float g_u[BB*DM*HH];               // folded key weights [b][m][h]
__device__ float g_denom[BB*HH];
__device__ float g_ypart[NCH*BB*HH*DM];       // per-chunk partial y_raw
__device__ float g_og[BB*DM];
__device__ float g_part1[4*BB*DM];            // wo partials [mp][b][o]
__device__ float g_part2[4*BB*DM];            // wp partials

// ---------------- K_prep: per (b,h): qg slice, u, inits ---------------------
// grid = 24 blocks, 256 thr.
__global__ void k_prep(const float* __restrict__ x,  const float* __restrict__ wqg,
                       const float* __restrict__ bqg, const float* __restrict__ wkg,
                       const float* __restrict__ bfc, float* __restrict__ out) {
    int blk = blockIdx.x; int b = blk / HH, h = blk % HH;
    int t = threadIdx.x;
    __shared__ float x0s[DM];
    __shared__ float qg_s[HD];
    __shared__ float redA[256];
    for (int i = t; i < DM; i += 256) x0s[i] = x[(size_t)b*SS*DM + i];
    __syncthreads();
    // phase A: qg[h*64+o] (coalesced wqg reads: consecutive lanes -> consecutive o)
    {
        int o = t & 63, part = t >> 6;
        float acc = 0.f;
        const float* wc = wqg + h*HD + o;
        #pragma unroll 8
        for (int j = 0; j < 192; j++) {
            int m = part*192 + j;
            acc += x0s[m] * wc[(size_t)m*DM];
        }
        redA[t] = acc;
    }
    __syncthreads();
    if (t < 64) {
        float q = redA[t] + redA[64+t] + redA[128+t] + redA[192+t];
        qg_s[t] = (q + bqg[h*HD + t]) * 0.125f;
    }
    __syncthreads();
    // phase B: u[b,m,h] = sum_d qg[d]*wkg[m, h*64+d]
    #pragma unroll
    for (int c = 0; c < 3; c++) {
        int m = c*256 + t;
        const float4* w4 = (const float4*)(wkg + (size_t)m*DM + h*HD);
        const float4* q4 = (const float4*)qg_s;
        float acc = 0.f;
        #pragma unroll
        for (int j = 0; j < 16; j++) {
            float4 w = w4[j], q = q4[j];
            acc += w.x*q.x + w.y*q.y + w.z*q.z + w.w*q.w;
        }
        g_u[((size_t)b*DM + m)*HH + h] = acc;
    }
    // inits (bias cancels in softmax so no sbias needed)
    if (h == 0) {
        if (t < HH) g_denom[b*HH + t] = 0.f;
        out[b*OUTN + t]       = bfc[t];
        out[b*OUTN + 256 + t] = bfc[256 + t];
    }
}

// ---------------- K_main: fused scores -> exp -> weighted x accumulation ----
// grid = BB*NCH = 256 blocks, 256 thr. Block handles 32 rows of one batch.
__global__ void k_main(const float* __restrict__ x) {
    int blk = blockIdx.x; int b = blk >> 7; int ch = blk & (NCH-1);
    int s0 = ch * CHROWS;
    int t = threadIdx.x;
    __shared__ __align__(16) float u_s[DM*HH];   // 36 KB, [m][h]
    __shared__ float e_s[HH*CHROWS];             // [h][s]
    {
        const float4* src = (const float4*)(g_u + (size_t)b*DM*HH);
        float4* dst = (float4*)u_s;
        for (int i = t; i < DM*HH/4; i += 256) dst[i] = src[i];
    }
    __syncthreads();

    // ---- phase 1: scores + exp. 8 threads per row, scalar-m interleave
    // (m = i*8+p gives conflict-free stride-12 LDS.128 on u_s).
    {
        int row = t >> 3, p = t & 7;
        const float* xr = x + ((size_t)b*SS + s0 + row)*DM;
        float acc[HH];
        #pragma unroll
        for (int h = 0; h < HH; h++) acc[h] = 0.f;
        #pragma unroll 4
        for (int i = 0; i < 96; i++) {
            int m = i*8 + p;
            float xv = xr[m];
            const float4* u4 = (const float4*)(u_s + m*HH);
            float4 a = u4[0], c = u4[1], e = u4[2];
            acc[0] += xv*a.x;  acc[1] += xv*a.y;  acc[2]  += xv*a.z;  acc[3]  += xv*a.w;
            acc[4] += xv*c.x;  acc[5] += xv*c.y;  acc[6]  += xv*c.z;  acc[7]  += xv*c.w;
            acc[8] += xv*e.x;  acc[9] += xv*e.y;  acc[10] += xv*e.z;  acc[11] += xv*e.w;
        }
        #pragma unroll
        for (int off = 4; off; off >>= 1)
            #pragma unroll
            for (int h = 0; h < HH; h++)
                acc[h] += __shfl_down_sync(0xffffffffu, acc[h], off, 8);
        if (p == 0) {
            #pragma unroll
            for (int h = 0; h < HH; h++)
                e_s[h*CHROWS + row] = __expf(acc[h]);   // scores ~O(1): no max needed
        }
    }
    __syncthreads();

    // ---- denominator partial
    if (t < HH) {
        float s = 0.f;
        #pragma unroll
        for (int j = 0; j < CHROWS; j++) s += e_s[t*CHROWS + j];
        atomicAdd(&g_denom[b*HH + t], s);
    }

    // ---- phase 2: ypart[h][m] = sum_s e[h][s] * x[s][m]. thread owns 3 m-cols.
    {
        float a2[3][HH];
        #pragma unroll
        for (int c = 0; c < 3; c++)
            #pragma unroll
            for (int h = 0; h < HH; h++) a2[c][h] = 0.f;
        const float* xp = x + ((size_t)b*SS + s0)*DM;
        for (int s = 0; s < CHROWS; s++) {
            float xv0 = xp[(size_t)s*DM + t];
            float xv1 = xp[(size_t)s*DM + 256 + t];
            float xv2 = xp[(size_t)s*DM + 512 + t];
            #pragma unroll
            for (int h = 0; h < HH; h++) {
                float eh = e_s[h*CHROWS + s];
                a2[0][h] += eh * xv0;
                a2[1][h] += eh * xv1;
                a2[2][h] += eh * xv2;
            }
        }
        size_t base = ((size_t)ch*BB + b)*HH;
        #pragma unroll
        for (int h = 0; h < HH; h++) {
            #pragma unroll
            for (int c = 0; c < 3; c++)
                g_ypart[(base + h)*DM + c*256 + t] = a2[c][h];
        }
    }
}

// ---------------- K_og: reduce ypart, /denom, GEMV wvg slice + bvg ---------
// grid = 24 blocks (b,h), 256 thr.
__global__ void k_og(const float* __restrict__ wvg, const float* __restrict__ bvg) {
    int blk = blockIdx.x; int b = blk / HH, h = blk % HH;
    int t = threadIdx.x;
    __shared__ float y_s[DM];
    __shared__ float red[256];
    float inv = 1.f / g_denom[b*HH + h];
    #pragma unroll
    for (int c = 0; c < 3; c++) {
        int m = c*256 + t;
        float s = 0.f;
        #pragma unroll 8
        for (int ch = 0; ch < NCH; ch++)
            s += g_ypart[(((size_t)ch*BB + b)*HH + h)*DM + m];
        y_s[m] = s * inv;
    }
    __syncthreads();
    int o = t & 63, part = t >> 6;
    float acc = 0.f;
    const float* wc = wvg + h*HD + o;
    #pragma unroll 8
    for (int j = 0; j < 192; j++) {
        int m = part*192 + j;
        acc += y_s[m] * wc[(size_t)m*DM];
    }
    red[t] = acc;
    __syncthreads();
    if (t < 64)
        g_og[b*DM + h*HD + t] = red[t] + red[64+t] + red[128+t] + red[192+t] + bvg[h*HD + t];
}

// ---------------- K_wo: attn0 partials (coalesced). grid=24 (b,oc3,mp4) -----
__global__ void k_wo(const float* __restrict__ wo) {
    int blk = blockIdx.x; int b = blk / 12; int r = blk % 12;
    int oc = r / 4, mp = r % 4;
    int t = threadIdx.x;
    __shared__ float in_s[192];
    if (t < 192) in_s[t] = g_og[b*DM + mp*192 + t];
    __syncthreads();
    int o = oc*256 + t;
    float acc = 0.f;
    const float* wc = wo + o;
    #pragma unroll 8
    for (int j = 0; j < 192; j++) {
        int m = mp*192 + j;
        acc += in_s[j] * wc[(size_t)m*DM];
    }
    g_part1[(mp*BB + b)*DM + o] = acc;
}

// ---------------- K_wp: pooled-pre partials. grid=24 ------------------------
__global__ void k_wp(const float* __restrict__ wp, const float* __restrict__ bo) {
    int blk = blockIdx.x; int b = blk / 12; int r = blk % 12;
    int oc = r / 4, mp = r % 4;
    int t = threadIdx.x;
    __shared__ float in_s[192];
    if (t < 192) {
        int m = mp*192 + t;
        in_s[t] = bo[m] + g_part1[(0*BB + b)*DM + m] + g_part1[(1*BB + b)*DM + m]
                        + g_part1[(2*BB + b)*DM + m] + g_part1[(3*BB + b)*DM + m];
    }
    __syncthreads();
    int o = oc*256 + t;
    float acc = 0.f;
    const float* wc = wp + o;
    #pragma unroll 8
    for (int j = 0; j < 192; j++) {
        int m = mp*192 + j;
        acc += in_s[j] * wc[(size_t)m*DM];
    }
    g_part2[(mp*BB + b)*DM + o] = acc;
}

// ---------------- K_wfc: final. grid=16 (b,oc2,mp4), atomicAdd into out -----
__global__ void k_wfc(const float* __restrict__ wfc, const float* __restrict__ bp,
                      float* __restrict__ out) {
    int blk = blockIdx.x; int b = blk / 8; int r = blk % 8;
    int oc = r / 4, mp = r % 4;
    int t = threadIdx.x;
    __shared__ float in_s[192];
    if (t < 192) {
        int m = mp*192 + t;
        float v = bp[m] + g_part2[(0*BB + b)*DM + m] + g_part2[(1*BB + b)*DM + m]
                        + g_part2[(2*BB + b)*DM + m] + g_part2[(3*BB + b)*DM + m];
        in_s[t] = tanhf(v);
    }
    __syncthreads();
    int o = oc*256 + t;
    float acc = 0.f;
    const float* wc = wfc + o;
    #pragma unroll 8
    for (int j = 0; j < 192; j++) {
        int m = mp*192 + j;
        acc += in_s[j] * wc[(size_t)m*OUTN];
    }
    atomicAdd(&out[b*OUTN + o], acc);
}

// ---------------- launch ----------------------------------------------------
extern "C" void kernel_launch(void* const* d_in, const int* in_sizes, int n_in,
                              void* d_out, int out_size) {
    const float* x   = (const float*)d_in[0];
    const float* wqg = (const float*)d_in[7];
    const float* bqg = (const float*)d_in[8];
    const float* wkg = (const float*)d_in[9];
    const float* wvg = (const float*)d_in[11];
    const float* bvg = (const float*)d_in[12];
    const float* wo  = (const float*)d_in[13];
    const float* bo  = (const float*)d_in[14];
    const float* wp  = (const float*)d_in[15];
    const float* bp  = (const float*)d_in[16];
    const float* wfc = (const float*)d_in[17];
    const float* bfc = (const float*)d_in[18];
    float* out = (float*)d_out;

    k_prep<<<BB*HH, 256>>>(x, wqg, bqg, wkg, bfc, out);
    k_main<<<BB*NCH, 256>>>(x);
    k_og<<<BB*HH, 256>>>(wvg, bvg);
    k_wo<<<24, 256>>>(wo);
    k_wp<<<24, 256>>>(wp, bo);
    k_wfc<<<16, 256>>>(wfc, bp, out);
}

// round 3
// speedup vs baseline: 2.1470x; 1.6065x over previous
#include <cuda_runtime.h>
#include <math.h>

#define BB 2
#define SS 4096
#define DM 768
#define HH 12
#define HD 64
#define OUTN 512
#define CHROWS 32            // rows per block in fused main kernel
#define NCH (SS/CHROWS)      // 128 chunks per batch

// ---------------- scratch ---------------------------------------------------
__device__ float g_u[BB*DM*HH];     // folded key weights [b][m][h]
__device__ float g_denom[BB*HH];
__device__ float g_y[BB*HH*DM];     // raw weighted sums (atomic accum)
__device__ float g_og[BB*DM];       // init bvg, atomic accum
__device__ float g_part1[BB*DM];    // init bo,  atomic accum (attn0)
__device__ float g_part2[BB*DM];    // init bp,  atomic accum (pre-tanh pooled)

// ---------------- K_prep: qg+u fold, plus all accumulator inits -------------
// grid = 24 blocks (b,h), 256 thr.
__global__ void k_prep(const float* __restrict__ x,  const float* __restrict__ wqg,
                       const float* __restrict__ bqg, const float* __restrict__ wkg,
                       const float* __restrict__ bvg, const float* __restrict__ bo,
                       const float* __restrict__ bp,  const float* __restrict__ bfc,
                       float* __restrict__ out) {
    int blk = blockIdx.x; int b = blk / HH, h = blk % HH;
    int t = threadIdx.x;

    // ---- distributed accumulator inits (independent of this block's b,h)
    {
        int i0 = blk*256 + t;                 // 0..6143
        if (i0 < 1536)       g_og[i0]          = bvg[i0 % DM];
        else if (i0 < 3072)  g_part1[i0-1536]  = bo[(i0-1536) % DM];
        else if (i0 < 4608)  g_part2[i0-3072]  = bp[(i0-3072) % DM];
        else if (i0 < 5632)  out[i0-4608]      = bfc[(i0-4608) % OUTN];
        else if (i0 < 5656)  g_denom[i0-5632]  = 0.f;
        for (int i = blk*256 + t; i < BB*HH*DM; i += 24*256) g_y[i] = 0.f;
    }

    __shared__ float x0s[DM];
    __shared__ float qg_s[HD];
    __shared__ float redA[256];
    for (int i = t; i < DM; i += 256) x0s[i] = x[(size_t)b*SS*DM + i];
    __syncthreads();
    // phase A: qg[h*64+o], coalesced wqg reads
    {
        int o = t & 63, part = t >> 6;
        float acc = 0.f;
        const float* wc = wqg + h*HD + o;
        #pragma unroll 8
        for (int j = 0; j < 192; j++) {
            int m = part*192 + j;
            acc += x0s[m] * wc[(size_t)m*DM];
        }
        redA[t] = acc;
    }
    __syncthreads();
    if (t < 64) {
        float q = redA[t] + redA[64+t] + redA[128+t] + redA[192+t];
        qg_s[t] = (q + bqg[h*HD + t]) * 0.125f;
    }
    __syncthreads();
    // phase B: u[b,m,h] = sum_d qg[d]*wkg[m, h*64+d]
    #pragma unroll
    for (int c = 0; c < 3; c++) {
        int m = c*256 + t;
        const float4* w4 = (const float4*)(wkg + (size_t)m*DM + h*HD);
        const float4* q4 = (const float4*)qg_s;
        float acc = 0.f;
        #pragma unroll
        for (int j = 0; j < 16; j++) {
            float4 w = w4[j], q = q4[j];
            acc += w.x*q.x + w.y*q.y + w.z*q.z + w.w*q.w;
        }
        g_u[((size_t)b*DM + m)*HH + h] = acc;
    }
}

// ---------------- K_main: fused scores -> exp -> weighted x accumulation ----
// grid = BB*NCH = 256 blocks, 256 thr.
__global__ void k_main(const float* __restrict__ x) {
    int blk = blockIdx.x; int b = blk >> 7; int ch = blk & (NCH-1);
    int s0 = ch * CHROWS;
    int t = threadIdx.x;
    __shared__ __align__(16) float u_s[DM*HH];   // 36 KB, [m][h]
    __shared__ float e_s[HH*CHROWS];             // [h][s]
    {
        const float4* src = (const float4*)(g_u + (size_t)b*DM*HH);
        float4* dst = (float4*)u_s;
        for (int i = t; i < DM*HH/4; i += 256) dst[i] = src[i];
    }
    __syncthreads();

    // ---- phase 1: scores + exp (8 threads/row)
    {
        int row = t >> 3, p = t & 7;
        const float* xr = x + ((size_t)b*SS + s0 + row)*DM;
        float acc[HH];
        #pragma unroll
        for (int h = 0; h < HH; h++) acc[h] = 0.f;
        #pragma unroll 4
        for (int i = 0; i < 96; i++) {
            int m = i*8 + p;
            float xv = xr[m];
            const float4* u4 = (const float4*)(u_s + m*HH);
            float4 a = u4[0], c = u4[1], e = u4[2];
            acc[0] += xv*a.x;  acc[1] += xv*a.y;  acc[2]  += xv*a.z;  acc[3]  += xv*a.w;
            acc[4] += xv*c.x;  acc[5] += xv*c.y;  acc[6]  += xv*c.z;  acc[7]  += xv*c.w;
            acc[8] += xv*e.x;  acc[9] += xv*e.y;  acc[10] += xv*e.z;  acc[11] += xv*e.w;
        }
        #pragma unroll
        for (int off = 4; off; off >>= 1)
            #pragma unroll
            for (int h = 0; h < HH; h++)
                acc[h] += __shfl_down_sync(0xffffffffu, acc[h], off, 8);
        if (p == 0) {
            #pragma unroll
            for (int h = 0; h < HH; h++)
                e_s[h*CHROWS + row] = __expf(acc[h]);
        }
    }
    __syncthreads();

    // ---- denominator partial
    if (t < HH) {
        float s = 0.f;
        #pragma unroll
        for (int j = 0; j < CHROWS; j++) s += e_s[t*CHROWS + j];
        atomicAdd(&g_denom[b*HH + t], s);
    }

    // ---- phase 2: accumulate y[b,h,m] directly (REDG, spread addresses)
    {
        float a2[3][HH];
        #pragma unroll
        for (int c = 0; c < 3; c++)
            #pragma unroll
            for (int h = 0; h < HH; h++) a2[c][h] = 0.f;
        const float* xp = x + ((size_t)b*SS + s0)*DM;
        for (int s = 0; s < CHROWS; s++) {
            float xv0 = xp[(size_t)s*DM + t];
            float xv1 = xp[(size_t)s*DM + 256 + t];
            float xv2 = xp[(size_t)s*DM + 512 + t];
            #pragma unroll
            for (int h = 0; h < HH; h++) {
                float eh = e_s[h*CHROWS + s];
                a2[0][h] += eh * xv0;
                a2[1][h] += eh * xv1;
                a2[2][h] += eh * xv2;
            }
        }
        #pragma unroll
        for (int h = 0; h < HH; h++) {
            size_t base = ((size_t)b*HH + h)*DM;
            #pragma unroll
            for (int c = 0; c < 3; c++)
                atomicAdd(&g_y[base + c*256 + t], a2[c][h]);
        }
    }
}

// ---------------- K_og: y/denom @ wvg slice -> og (m-split, atomic) ---------
// grid = BB*HH*4 = 96 blocks, 256 thr. Block owns m range [sub*192, +192).
__global__ void k_og(const float* __restrict__ wvg) {
    int blk = blockIdx.x;
    int b = blk / (HH*4); int r = blk % (HH*4);
    int h = r >> 2; int sub = r & 3;
    int t = threadIdx.x;
    __shared__ float y_s[192];
    __shared__ float red[256];
    float inv = 1.f / g_denom[b*HH + h];
    if (t < 192) y_s[t] = g_y[((size_t)b*HH + h)*DM + sub*192 + t] * inv;
    __syncthreads();
    int o = t & 63, q = t >> 6;          // 4 quarters of 48 m each
    float acc = 0.f;
    const float* wc = wvg + h*HD + o;
    #pragma unroll 8
    for (int j = 0; j < 48; j++) {
        int m = sub*192 + q*48 + j;
        acc += y_s[q*48 + j] * wc[(size_t)m*DM];
    }
    red[t] = acc;
    __syncthreads();
    if (t < 64)
        atomicAdd(&g_og[b*DM + h*HD + t], red[t] + red[64+t] + red[128+t] + red[192+t]);
}

// ---------------- split 768->768 GEMV: grid = BB*3*24 = 144 blocks ----------
__global__ void k_gemv_split(const float* __restrict__ in, const float* __restrict__ w,
                             float* __restrict__ outacc) {
    int blk = blockIdx.x;
    int b  = blk / 72; int r = blk % 72;
    int oc = r / 24;   int mc = r % 24;    // o chunk of 256, m chunk of 32
    int t = threadIdx.x;
    __shared__ float in_s[32];
    if (t < 32) in_s[t] = in[b*DM + mc*32 + t];
    __syncthreads();
    int o = oc*256 + t;
    float acc = 0.f;
    const float* wc = w + o;
    #pragma unroll
    for (int j = 0; j < 32; j++)
        acc += in_s[j] * wc[(size_t)(mc*32 + j)*DM];
    atomicAdd(&outacc[b*DM + o], acc);
}

// ---------------- K_wfc: tanh(part2) @ wfc -> out. grid = BB*2*24 = 96 ------
__global__ void k_wfc(const float* __restrict__ wfc, float* __restrict__ out) {
    int blk = blockIdx.x;
    int b  = blk / 48; int r = blk % 48;
    int oc = r / 24;   int mc = r % 24;
    int t = threadIdx.x;
    __shared__ float in_s[32];
    if (t < 32) in_s[t] = tanhf(g_part2[b*DM + mc*32 + t]);
    __syncthreads();
    int o = oc*256 + t;
    float acc = 0.f;
    const float* wc = wfc + o;
    #pragma unroll
    for (int j = 0; j < 32; j++)
        acc += in_s[j] * wc[(size_t)(mc*32 + j)*OUTN];
    atomicAdd(&out[b*OUTN + o], acc);
}

// ---------------- launch ----------------------------------------------------
extern "C" void kernel_launch(void* const* d_in, const int* in_sizes, int n_in,
                              void* d_out, int out_size) {
    const float* x   = (const float*)d_in[0];
    const float* wqg = (const float*)d_in[7];
    const float* bqg = (const float*)d_in[8];
    const float* wkg = (const float*)d_in[9];
    const float* wvg = (const float*)d_in[11];
    const float* bvg = (const float*)d_in[12];
    const float* wo  = (const float*)d_in[13];
    const float* bo  = (const float*)d_in[14];
    const float* wp  = (const float*)d_in[15];
    const float* bp  = (const float*)d_in[16];
    const float* wfc = (const float*)d_in[17];
    const float* bfc = (const float*)d_in[18];
    float* out = (float*)d_out;

    float *p_og, *p_part1, *p_part2;
    cudaGetSymbolAddress((void**)&p_og, g_og);
    cudaGetSymbolAddress((void**)&p_part1, g_part1);
    cudaGetSymbolAddress((void**)&p_part2, g_part2);

    k_prep<<<BB*HH, 256>>>(x, wqg, bqg, wkg, bvg, bo, bp, bfc, out);
    k_main<<<BB*NCH, 256>>>(x);
    k_og<<<BB*HH*4, 256>>>(wvg);
    k_gemv_split<<<144, 256>>>(p_og, wo, p_part1);      // attn0
    k_gemv_split<<<144, 256>>>(p_part1, wp, p_part2);   // pre-tanh pooled
    k_wfc<<<96, 256>>>(wfc, out);
}

// round 4
// speedup vs baseline: 2.3137x; 1.0776x over previous
#include <cuda_runtime.h>
#include <math.h>

#define BB 2
#define SS 4096
#define DM 768
#define HH 12
#define HD 64
#define OUTN 512
#define GRID 128
#define NTHR 256
#define CHROWS 64
#define NCH (SS/CHROWS)     // 64 chunks per batch; BB*NCH = 128 = GRID

// ---------------- scratch ---------------------------------------------------
__device__ float g_qg[BB*DM];                 // scaled q row0
__device__ float g_u[BB*DM*HH];               // folded key weights [b][m][h]
__device__ float g_denom[BB*HH];
__device__ float g_ypart[NCH*BB*HH*DM];       // per-chunk partial weighted sums
__device__ float g_og[BB*DM];                 // init bvg, atomic accum
__device__ float g_part1[BB*DM];              // init bo,  atomic accum
__device__ float g_part2[BB*DM];              // init bp,  atomic accum
__device__ unsigned g_cnt;                    // monotonic grid-barrier counter

// ---------------- f32x2 helpers ---------------------------------------------
#define FMA2(d,a,b,c) asm("fma.rn.f32x2 %0, %1, %2, %3;" : "=l"(d) : "l"(a), "l"(b), "l"(c))
#define PACK2(d,lo,hi) asm("mov.b64 %0, {%1,%2};" : "=l"(d) : "f"(lo), "f"(hi))
#define UNPK2(lo,hi,s) asm("mov.b64 {%0,%1}, %2;" : "=f"(lo), "=f"(hi) : "l"(s))

// ---------------- grid barrier (monotonic counter; replay-safe) -------------
__device__ __forceinline__ void gbar() {
    __syncthreads();
    if (threadIdx.x == 0) {
        __threadfence();
        unsigned arr = atomicAdd(&g_cnt, 1u);
        unsigned target = (arr / GRID + 1u) * GRID;
        while (*((volatile unsigned*)&g_cnt) < target) __nanosleep(32);
        __threadfence();
    }
    __syncthreads();
}

__global__ __launch_bounds__(NTHR)
void k_mega(const float* __restrict__ x,   const float* __restrict__ wqg,
            const float* __restrict__ bqg, const float* __restrict__ wkg,
            const float* __restrict__ wvg, const float* __restrict__ bvg,
            const float* __restrict__ wo,  const float* __restrict__ bo,
            const float* __restrict__ wp,  const float* __restrict__ bp,
            const float* __restrict__ wfc, const float* __restrict__ bfc,
            float* __restrict__ out) {
    __shared__ __align__(16) float sm[9984];   // 39 KB union, per-stage reuse
    const int blk = blockIdx.x;
    const int t = threadIdx.x;

    // ======== Stage 0: accumulator inits + qg (blocks 0..23) ================
    {
        int i = blk*NTHR + t;                              // 0..32767
        int j = i;
        if (j < 1536)       g_og[j]         = bvg[j % DM];
        else if (j < 3072)  g_part1[j-1536] = bo[(j-1536) % DM];
        else if (j < 4608)  g_part2[j-3072] = bp[(j-3072) % DM];
        else if (j < 5632)  out[j-4608]     = bfc[(j-4608) % OUTN];
        else if (j < 5656)  g_denom[j-5632] = 0.f;
    }
    if (blk < 24) {
        int b = blk / 12, h = blk % 12;
        float* x0s = sm; float* redA = sm + 768;
        for (int i = t; i < DM; i += NTHR) x0s[i] = x[(size_t)b*SS*DM + i];
        __syncthreads();
        int o = t & 63, part = t >> 6;
        float acc = 0.f;
        const float* wc = wqg + h*HD + o;
        #pragma unroll 32
        for (int j = 0; j < 192; j++) {
            int m = part*192 + j;
            acc += x0s[m] * wc[(size_t)m*DM];
        }
        redA[t] = acc;
        __syncthreads();
        if (t < 64)
            g_qg[b*DM + h*HD + t] =
                (redA[t] + redA[64+t] + redA[128+t] + redA[192+t] + bqg[h*HD + t]) * 0.125f;
    }
    gbar();

    // ======== Stage 1: u[b,m,h] = qg[b,h,:]·wkg[m,h*64:] ====================
    {
        int b = blk >> 6, mc = blk & 63;     // 12 m's per block
        float* qgs = sm;
        for (int i = t; i < DM; i += NTHR) qgs[i] = g_qg[b*DM + i];
        __syncthreads();
        if (t < 144) {
            int mi = t / 12, h = t % 12;
            int m = mc*12 + mi;
            const float* w = wkg + (size_t)m*DM + h*HD;
            const float* q = qgs + h*HD;
            float acc = 0.f;
            #pragma unroll
            for (int d = 0; d < HD; d++) acc += q[d] * w[d];
            g_u[((size_t)b*DM + m)*HH + h] = acc;
        }
    }
    gbar();

    // ======== Stage 2: fused scores -> exp -> weighted-sum partials =========
    {
        int b = blk >> 6, ch = blk & (NCH-1);
        int s0 = ch * CHROWS;
        float* u_s = sm;                 // [m][12], 9216 floats
        float* e_s = sm + 9216;          // [s][12], 768 floats
        {
            const float4* src = (const float4*)(g_u + (size_t)b*DM*HH);
            float4* dst = (float4*)u_s;
            for (int i = t; i < DM*HH/4; i += NTHR) dst[i] = src[i];
        }
        __syncthreads();

        // ---- phase 1: 8 lanes per row-pair, rows rg and rg+32, f32x2 heads
        {
            int rg = t >> 3, p = t & 7;
            const float* xr0 = x + ((size_t)b*SS + s0 + rg)*DM;
            const float* xr1 = xr0 + (size_t)32*DM;
            unsigned long long aA[6], aB[6];
            #pragma unroll
            for (int k = 0; k < 6; k++) { aA[k] = 0ull; aB[k] = 0ull; }
            #pragma unroll 4
            for (int i = 0; i < 96; i++) {
                int m = i*8 + p;
                float xv0 = xr0[m], xv1 = xr1[m];
                unsigned long long xx0, xx1;
                PACK2(xx0, xv0, xv0); PACK2(xx1, xv1, xv1);
                const ulonglong2* u2p = (const ulonglong2*)(u_s + m*HH);
                ulonglong2 w0 = u2p[0], w1 = u2p[1], w2 = u2p[2];
                FMA2(aA[0], xx0, w0.x, aA[0]); FMA2(aA[1], xx0, w0.y, aA[1]);
                FMA2(aA[2], xx0, w1.x, aA[2]); FMA2(aA[3], xx0, w1.y, aA[3]);
                FMA2(aA[4], xx0, w2.x, aA[4]); FMA2(aA[5], xx0, w2.y, aA[5]);
                FMA2(aB[0], xx1, w0.x, aB[0]); FMA2(aB[1], xx1, w0.y, aB[1]);
                FMA2(aB[2], xx1, w1.x, aB[2]); FMA2(aB[3], xx1, w1.y, aB[3]);
                FMA2(aB[4], xx1, w2.x, aB[4]); FMA2(aB[5], xx1, w2.y, aB[5]);
            }
            float vA[12], vB[12];
            #pragma unroll
            for (int k = 0; k < 6; k++) {
                UNPK2(vA[2*k], vA[2*k+1], aA[k]);
                UNPK2(vB[2*k], vB[2*k+1], aB[k]);
            }
            #pragma unroll
            for (int off = 4; off; off >>= 1)
                #pragma unroll
                for (int h = 0; h < HH; h++) {
                    vA[h] += __shfl_down_sync(0xffffffffu, vA[h], off, 8);
                    vB[h] += __shfl_down_sync(0xffffffffu, vB[h], off, 8);
                }
            if (p == 0) {
                #pragma unroll
                for (int h = 0; h < HH; h++) {
                    e_s[rg*HH + h]      = __expf(vA[h]);
                    e_s[(rg+32)*HH + h] = __expf(vB[h]);
                }
            }
        }
        __syncthreads();

        // ---- denominator partials
        if (t < HH) {
            float s = 0.f;
            #pragma unroll 8
            for (int j = 0; j < CHROWS; j++) s += e_s[j*HH + t];
            atomicAdd(&g_denom[b*HH + t], s);
        }

        // ---- phase 2: ypart[h][m] = sum_s e[s][h]*x[s][m], f32x2 head pairs
        {
            unsigned long long acc[3][6];
            #pragma unroll
            for (int c = 0; c < 3; c++)
                #pragma unroll
                for (int k = 0; k < 6; k++) acc[c][k] = 0ull;
            const float* xp = x + ((size_t)b*SS + s0)*DM;
            for (int s = 0; s < CHROWS; s++) {
                float xv0 = xp[(size_t)s*DM + t];
                float xv1 = xp[(size_t)s*DM + 256 + t];
                float xv2 = xp[(size_t)s*DM + 512 + t];
                unsigned long long xx0, xx1, xx2;
                PACK2(xx0, xv0, xv0); PACK2(xx1, xv1, xv1); PACK2(xx2, xv2, xv2);
                const ulonglong2* e2 = (const ulonglong2*)(e_s + s*HH);
                ulonglong2 e01 = e2[0], e23 = e2[1], e45 = e2[2];
                FMA2(acc[0][0], e01.x, xx0, acc[0][0]); FMA2(acc[0][1], e01.y, xx0, acc[0][1]);
                FMA2(acc[0][2], e23.x, xx0, acc[0][2]); FMA2(acc[0][3], e23.y, xx0, acc[0][3]);
                FMA2(acc[0][4], e45.x, xx0, acc[0][4]); FMA2(acc[0][5], e45.y, xx0, acc[0][5]);
                FMA2(acc[1][0], e01.x, xx1, acc[1][0]); FMA2(acc[1][1], e01.y, xx1, acc[1][1]);
                FMA2(acc[1][2], e23.x, xx1, acc[1][2]); FMA2(acc[1][3], e23.y, xx1, acc[1][3]);
                FMA2(acc[1][4], e45.x, xx1, acc[1][4]); FMA2(acc[1][5], e45.y, xx1, acc[1][5]);
                FMA2(acc[2][0], e01.x, xx2, acc[2][0]); FMA2(acc[2][1], e01.y, xx2, acc[2][1]);
                FMA2(acc[2][2], e23.x, xx2, acc[2][2]); FMA2(acc[2][3], e23.y, xx2, acc[2][3]);
                FMA2(acc[2][4], e45.x, xx2, acc[2][4]); FMA2(acc[2][5], e45.y, xx2, acc[2][5]);
            }
            size_t base = ((size_t)ch*BB + b)*HH;
            #pragma unroll
            for (int c = 0; c < 3; c++)
                #pragma unroll
                for (int k = 0; k < 6; k++) {
                    float f0, f1;
                    UNPK2(f0, f1, acc[c][k]);
                    g_ypart[(base + 2*k  )*DM + c*256 + t] = f0;
                    g_ypart[(base + 2*k+1)*DM + c*256 + t] = f1;
                }
        }
    }
    gbar();

    // ======== Stage 3: og = (y/denom) @ wvg slice (+bvg preloaded) ==========
    if (blk < 96) {
        int b = blk / 48; int r = blk % 48;
        int h = r >> 2; int sub = r & 3;
        float* y_s = sm; float* red = sm + 192;
        float inv = 1.f / __ldcg(&g_denom[b*HH + h]);
        if (t < 192) {
            float s = 0.f;
            #pragma unroll 8
            for (int ch = 0; ch < NCH; ch++)
                s += g_ypart[(((size_t)ch*BB + b)*HH + h)*DM + sub*192 + t];
            y_s[t] = s * inv;
        }
        __syncthreads();
        int o = t & 63, q = t >> 6;
        float acc = 0.f;
        const float* wc = wvg + h*HD + o;
        #pragma unroll
        for (int j = 0; j < 48; j++) {
            int m = sub*192 + q*48 + j;
            acc += y_s[q*48 + j] * wc[(size_t)m*DM];
        }
        red[t] = acc;
        __syncthreads();
        if (t < 64)
            atomicAdd(&g_og[b*DM + h*HD + t], red[t] + red[64+t] + red[128+t] + red[192+t]);
    }
    gbar();

    // ======== Stage 4: attn0 partials: og @ wo ==============================
    for (int slot = blk; slot < 144; slot += GRID) {
        int b = slot / 72; int r = slot % 72;
        int oc = r / 24;   int mc = r % 24;
        float* in_s = sm;
        __syncthreads();
        if (t < 32) in_s[t] = __ldcg(&g_og[b*DM + mc*32 + t]);
        __syncthreads();
        int o = oc*256 + t;
        float acc = 0.f;
        const float* wc = wo + o;
        #pragma unroll
        for (int j = 0; j < 32; j++)
            acc += in_s[j] * wc[(size_t)(mc*32 + j)*DM];
        atomicAdd(&g_part1[b*DM + o], acc);
    }
    gbar();

    // ======== Stage 5: pre-tanh pooled partials: attn0 @ wp =================
    for (int slot = blk; slot < 144; slot += GRID) {
        int b = slot / 72; int r = slot % 72;
        int oc = r / 24;   int mc = r % 24;
        float* in_s = sm;
        __syncthreads();
        if (t < 32) in_s[t] = __ldcg(&g_part1[b*DM + mc*32 + t]);
        __syncthreads();
        int o = oc*256 + t;
        float acc = 0.f;
        const float* wc = wp + o;
        #pragma unroll
        for (int j = 0; j < 32; j++)
            acc += in_s[j] * wc[(size_t)(mc*32 + j)*DM];
        atomicAdd(&g_part2[b*DM + o], acc);
    }
    gbar();

    // ======== Stage 6: out += tanh(part2) @ wfc =============================
    if (blk < 96) {
        int b = blk / 48; int r = blk % 48;
        int oc = r / 24;  int mc = r % 24;
        float* in_s = sm;
        if (t < 32) in_s[t] = tanhf(__ldcg(&g_part2[b*DM + mc*32 + t]));
        __syncthreads();
        int o = oc*256 + t;
        float acc = 0.f;
        const float* wc = wfc + o;
        #pragma unroll
        for (int j = 0; j < 32; j++)
            acc += in_s[j] * wc[(size_t)(mc*32 + j)*OUTN];
        atomicAdd(&out[b*OUTN + o], acc);
    }
}

// ---------------- launch ----------------------------------------------------
extern "C" void kernel_launch(void* const* d_in, const int* in_sizes, int n_in,
                              void* d_out, int out_size) {
    const float* x   = (const float*)d_in[0];
    const float* wqg = (const float*)d_in[7];
    const float* bqg = (const float*)d_in[8];
    const float* wkg = (const float*)d_in[9];
    const float* wvg = (const float*)d_in[11];
    const float* bvg = (const float*)d_in[12];
    const float* wo  = (const float*)d_in[13];
    const float* bo  = (const float*)d_in[14];
    const float* wp  = (const float*)d_in[15];
    const float* bp  = (const float*)d_in[16];
    const float* wfc = (const float*)d_in[17];
    const float* bfc = (const float*)d_in[18];
    float* out = (float*)d_out;

    k_mega<<<GRID, NTHR>>>(x, wqg, bqg, wkg, wvg, bvg, wo, bo, wp, bp, wfc, bfc, out);
}

// round 5
// speedup vs baseline: 2.4241x; 1.0477x over previous
#include <cuda_runtime.h>
#include <math.h>

#define BB 2
#define SS 4096
#define DM 768
#define HH 12
#define HD 64
#define OUTN 512
#define GRID 128
#define NTHR 512
#define CHROWS 64
#define NCH (SS/CHROWS)     // 64 chunks per batch; BB*NCH = 128 = GRID
#define NCHW (NCH*2)        // 128 ypart slots (s-halves)

// ---------------- scratch ---------------------------------------------------
__device__ float g_qg[BB*DM];                 // scaled q row0
__device__ float g_u[BB*DM*HH];               // folded key weights [b][m][h]
__device__ float g_denom[BB*HH];
__device__ float g_ypart[NCHW*BB*HH*DM];      // per-halfchunk partial sums
__device__ float g_og[BB*DM];                 // init bvg, atomic accum
__device__ float g_part1[BB*DM];              // init bo,  atomic accum
__device__ float g_part2[BB*DM];              // init bp,  atomic accum
__device__ unsigned g_cnt;                    // monotonic grid-barrier counter

// ---------------- f32x2 helpers ---------------------------------------------
#define FMA2(d,a,b,c) asm("fma.rn.f32x2 %0, %1, %2, %3;" : "=l"(d) : "l"(a), "l"(b), "l"(c))
#define PACK2(d,lo,hi) asm("mov.b64 %0, {%1,%2};" : "=l"(d) : "f"(lo), "f"(hi))
#define UNPK2(lo,hi,s) asm("mov.b64 {%0,%1}, %2;" : "=f"(lo), "=f"(hi) : "l"(s))

// ---------------- grid barrier (monotonic counter; replay-safe) -------------
__device__ __forceinline__ void gbar() {
    __syncthreads();
    if (threadIdx.x == 0) {
        __threadfence();
        unsigned arr = atomicAdd(&g_cnt, 1u);
        unsigned target = (arr / GRID + 1u) * GRID;
        while (*((volatile unsigned*)&g_cnt) < target) __nanosleep(32);
        __threadfence();
    }
    __syncthreads();
}

__global__ __launch_bounds__(NTHR)
void k_mega(const float* __restrict__ x,   const float* __restrict__ wqg,
            const float* __restrict__ bqg, const float* __restrict__ wkg,
            const float* __restrict__ wvg, const float* __restrict__ bvg,
            const float* __restrict__ wo,  const float* __restrict__ bo,
            const float* __restrict__ wp,  const float* __restrict__ bp,
            const float* __restrict__ wfc, const float* __restrict__ bfc,
            float* __restrict__ out) {
    __shared__ __align__(16) float sm[9984];   // ~39 KB union, per-stage reuse
    const int blk = blockIdx.x;
    const int t = threadIdx.x;

    // ======== Stage 0: accumulator inits + qg (blocks 0..23) ================
    {
        int j = blk*NTHR + t;
        if (j < 1536)       g_og[j]         = bvg[j % DM];
        else if (j < 3072)  g_part1[j-1536] = bo[(j-1536) % DM];
        else if (j < 4608)  g_part2[j-3072] = bp[(j-3072) % DM];
        else if (j < 5632)  out[j-4608]     = bfc[(j-4608) % OUTN];
        else if (j < 5656)  g_denom[j-5632] = 0.f;
    }
    if (blk < 24) {
        int b = blk / 12, h = blk % 12;
        float* x0s = sm; float* redA = sm + 768;
        for (int i = t; i < DM; i += NTHR) x0s[i] = x[(size_t)b*SS*DM + i];
        __syncthreads();
        int o = t & 63, part = t >> 6;                 // 8 parts of 96 m
        float acc = 0.f;
        const float* wc = wqg + h*HD + o;
        #pragma unroll 16
        for (int j = 0; j < 96; j++) {
            int m = part*96 + j;
            acc += x0s[m] * wc[(size_t)m*DM];
        }
        redA[t] = acc;
        __syncthreads();
        if (t < 64) {
            float s = bqg[h*HD + t];
            #pragma unroll
            for (int k = 0; k < 8; k++) s += redA[k*64 + t];
            g_qg[b*DM + h*HD + t] = s * 0.125f;
        }
    }
    gbar();

    // ======== Stage 1: u[b,m,h] = qg[b,h,:]·wkg[m,h*64:] ====================
    {
        int b = blk >> 6, mc = blk & 63;     // 12 m's per block
        float* qgs = sm;
        for (int i = t; i < DM; i += NTHR) qgs[i] = g_qg[b*DM + i];
        __syncthreads();
        if (t < 144) {
            int mi = t / 12, h = t % 12;
            int m = mc*12 + mi;
            const float* w = wkg + (size_t)m*DM + h*HD;
            const float* q = qgs + h*HD;
            float acc = 0.f;
            #pragma unroll
            for (int d = 0; d < HD; d++) acc += q[d] * w[d];
            g_u[((size_t)b*DM + m)*HH + h] = acc;
        }
    }
    gbar();

    // ======== Stage 2: fused scores -> exp -> weighted-sum partials =========
    {
        int b = blk >> 6, ch = blk & (NCH-1);
        int s0 = ch * CHROWS;
        float* u_s = sm;                 // [m][12], 9216 floats
        float* e_s = sm + 9216;          // [s][12], 768 floats
        {
            const float4* src = (const float4*)(g_u + (size_t)b*DM*HH);
            float4* dst = (float4*)u_s;
            for (int i = t; i < DM*HH/4; i += NTHR) dst[i] = src[i];
        }
        __syncthreads();

        // ---- phase 1: 64 row-groups x 8 lanes, f32x2 head pairs
        {
            int rg = t >> 3, p = t & 7;
            const float* xr = x + ((size_t)b*SS + s0 + rg)*DM;
            unsigned long long aA[6];
            #pragma unroll
            for (int k = 0; k < 6; k++) aA[k] = 0ull;
            #pragma unroll 8
            for (int i = 0; i < 96; i++) {
                int m = i*8 + p;
                float xv = xr[m];
                unsigned long long xx;
                PACK2(xx, xv, xv);
                const ulonglong2* u2p = (const ulonglong2*)(u_s + m*HH);
                ulonglong2 w0 = u2p[0], w1 = u2p[1], w2 = u2p[2];
                FMA2(aA[0], xx, w0.x, aA[0]); FMA2(aA[1], xx, w0.y, aA[1]);
                FMA2(aA[2], xx, w1.x, aA[2]); FMA2(aA[3], xx, w1.y, aA[3]);
                FMA2(aA[4], xx, w2.x, aA[4]); FMA2(aA[5], xx, w2.y, aA[5]);
            }
            float vA[12];
            #pragma unroll
            for (int k = 0; k < 6; k++) UNPK2(vA[2*k], vA[2*k+1], aA[k]);
            #pragma unroll
            for (int off = 4; off; off >>= 1)
                #pragma unroll
                for (int h = 0; h < HH; h++)
                    vA[h] += __shfl_down_sync(0xffffffffu, vA[h], off, 8);
            if (p == 0) {
                #pragma unroll
                for (int h = 0; h < HH; h++)
                    e_s[rg*HH + h] = __expf(vA[h]);
            }
        }
        __syncthreads();

        // ---- denominator partials
        if (t < HH) {
            float s = 0.f;
            #pragma unroll 8
            for (int j = 0; j < CHROWS; j++) s += e_s[j*HH + t];
            atomicAdd(&g_denom[b*HH + t], s);
        }

        // ---- phase 2: s-halves; ypart[h][m] = sum_s e[s][h]*x[s][m]
        {
            int half = t >> 8, tc = t & 255;
            unsigned long long acc[3][6];
            #pragma unroll
            for (int c = 0; c < 3; c++)
                #pragma unroll
                for (int k = 0; k < 6; k++) acc[c][k] = 0ull;
            const float* xp = x + ((size_t)b*SS + s0 + half*32)*DM;
            const float* ep = e_s + half*32*HH;
            for (int s = 0; s < 32; s++) {
                float xv0 = xp[(size_t)s*DM + tc];
                float xv1 = xp[(size_t)s*DM + 256 + tc];
                float xv2 = xp[(size_t)s*DM + 512 + tc];
                unsigned long long xx0, xx1, xx2;
                PACK2(xx0, xv0, xv0); PACK2(xx1, xv1, xv1); PACK2(xx2, xv2, xv2);
                const ulonglong2* e2 = (const ulonglong2*)(ep + s*HH);
                ulonglong2 e01 = e2[0], e23 = e2[1], e45 = e2[2];
                FMA2(acc[0][0], e01.x, xx0, acc[0][0]); FMA2(acc[0][1], e01.y, xx0, acc[0][1]);
                FMA2(acc[0][2], e23.x, xx0, acc[0][2]); FMA2(acc[0][3], e23.y, xx0, acc[0][3]);
                FMA2(acc[0][4], e45.x, xx0, acc[0][4]); FMA2(acc[0][5], e45.y, xx0, acc[0][5]);
                FMA2(acc[1][0], e01.x, xx1, acc[1][0]); FMA2(acc[1][1], e01.y, xx1, acc[1][1]);
                FMA2(acc[1][2], e23.x, xx1, acc[1][2]); FMA2(acc[1][3], e23.y, xx1, acc[1][3]);
                FMA2(acc[1][4], e45.x, xx1, acc[1][4]); FMA2(acc[1][5], e45.y, xx1, acc[1][5]);
                FMA2(acc[2][0], e01.x, xx2, acc[2][0]); FMA2(acc[2][1], e01.y, xx2, acc[2][1]);
                FMA2(acc[2][2], e23.x, xx2, acc[2][2]); FMA2(acc[2][3], e23.y, xx2, acc[2][3]);
                FMA2(acc[2][4], e45.x, xx2, acc[2][4]); FMA2(acc[2][5], e45.y, xx2, acc[2][5]);
            }
            size_t base = ((size_t)(ch*2 + half)*BB + b)*HH;
            #pragma unroll
            for (int c = 0; c < 3; c++)
                #pragma unroll
                for (int k = 0; k < 6; k++) {
                    float f0, f1;
                    UNPK2(f0, f1, acc[c][k]);
                    g_ypart[(base + 2*k  )*DM + c*256 + tc] = f0;
                    g_ypart[(base + 2*k+1)*DM + c*256 + tc] = f1;
                }
        }
    }
    gbar();

    // ======== Stage 3: og = (y/denom) @ wvg slice (+bvg preloaded) ==========
    if (blk < 96) {
        int b = blk / 48; int r = blk % 48;
        int h = r >> 2; int sub = r & 3;
        float* y_s = sm; float* redR = sm + 192; float* redG = sm + 576;
        float inv = 1.f / __ldcg(&g_denom[b*HH + h]);
        if (t < 384) {
            int e = t % 192, prt = t / 192;
            float s = 0.f;
            #pragma unroll 8
            for (int c2 = prt; c2 < NCHW; c2 += 2)
                s += g_ypart[(((size_t)c2*BB + b)*HH + h)*DM + sub*192 + e];
            redR[t] = s;
        }
        __syncthreads();
        if (t < 192) y_s[t] = (redR[t] + redR[t+192]) * inv;
        __syncthreads();
        int o = t & 63, q = t >> 6;          // 8 parts of 24 m
        float acc = 0.f;
        const float* wc = wvg + h*HD + o;
        #pragma unroll
        for (int j = 0; j < 24; j++) {
            int ml = q*24 + j;
            acc += y_s[ml] * wc[(size_t)(sub*192 + ml)*DM];
        }
        redG[t] = acc;
        __syncthreads();
        if (t < 64) {
            float s = 0.f;
            #pragma unroll
            for (int k = 0; k < 8; k++) s += redG[k*64 + t];
            atomicAdd(&g_og[b*DM + h*HD + t], s);
        }
    }
    gbar();

    // ======== Stage 4: attn0 partials: og @ wo (72 slots) ===================
    if (blk < 72) {
        int b = blk / 36; int r = blk % 36;
        int oc = r / 12;  int mcp = r % 12;      // 64-m chunk
        float* in_s = sm;
        if (t < 64) in_s[t] = __ldcg(&g_og[b*DM + mcp*64 + t]);
        __syncthreads();
        int o = oc*256 + (t & 255), mh = t >> 8;
        float acc = 0.f;
        const float* wc = wo + o;
        #pragma unroll
        for (int j = 0; j < 32; j++)
            acc += in_s[mh*32 + j] * wc[(size_t)(mcp*64 + mh*32 + j)*DM];
        atomicAdd(&g_part1[b*DM + o], acc);
    }
    gbar();

    // ======== Stage 5: pre-tanh pooled partials: attn0 @ wp =================
    if (blk < 72) {
        int b = blk / 36; int r = blk % 36;
        int oc = r / 12;  int mcp = r % 12;
        float* in_s = sm;
        if (t < 64) in_s[t] = __ldcg(&g_part1[b*DM + mcp*64 + t]);
        __syncthreads();
        int o = oc*256 + (t & 255), mh = t >> 8;
        float acc = 0.f;
        const float* wc = wp + o;
        #pragma unroll
        for (int j = 0; j < 32; j++)
            acc += in_s[mh*32 + j] * wc[(size_t)(mcp*64 + mh*32 + j)*DM];
        atomicAdd(&g_part2[b*DM + o], acc);
    }
    gbar();

    // ======== Stage 6: out += tanh(part2) @ wfc (48 slots) ==================
    if (blk < 48) {
        int b = blk / 24; int r = blk % 24;
        int oc = r / 12;  int mcp = r % 12;
        float* in_s = sm;
        if (t < 64) in_s[t] = tanhf(__ldcg(&g_part2[b*DM + mcp*64 + t]));
        __syncthreads();
        int o = oc*256 + (t & 255), mh = t >> 8;
        float acc = 0.f;
        const float* wc = wfc + o;
        #pragma unroll
        for (int j = 0; j < 32; j++)
            acc += in_s[mh*32 + j] * wc[(size_t)(mcp*64 + mh*32 + j)*OUTN];
        atomicAdd(&out[b*OUTN + o], acc);
    }
}

// ---------------- launch ----------------------------------------------------
extern "C" void kernel_launch(void* const* d_in, const int* in_sizes, int n_in,
                              void* d_out, int out_size) {
    const float* x   = (const float*)d_in[0];
    const float* wqg = (const float*)d_in[7];
    const float* bqg = (const float*)d_in[8];
    const float* wkg = (const float*)d_in[9];
    const float* wvg = (const float*)d_in[11];
    const float* bvg = (const float*)d_in[12];
    const float* wo  = (const float*)d_in[13];
    const float* bo  = (const float*)d_in[14];
    const float* wp  = (const float*)d_in[15];
    const float* bp  = (const float*)d_in[16];
    const float* wfc = (const float*)d_in[17];
    const float* bfc = (const float*)d_in[18];
    float* out = (float*)d_out;

    k_mega<<<GRID, NTHR>>>(x, wqg, bqg, wkg, wvg, bvg, wo, bo, wp, bp, wfc, bfc, out);
}